// round 3
// baseline (speedup 1.0000x reference)
#include <cuda_runtime.h>
#include <cstdint>

// ExodusNeuron scan, R3: one warp per block (fully decoupled), 5-stage
// cp.async smem ring (prefetch distance 4 tiles >> DRAM latency + arrival
// jitter), LDS lookahead of 4 steps.
//
// Numerics (bit-exact vs reference, rel_err 0.0 in R1/R2):
//   xi  = x*w                  (rounded mul)
//   vs  = fma(alpha, vs, xi)
//   vmp = fma(alpha, vm, vs)
//   spk = vmp >= 1 ; vm = spk ? vmp-1 : vmp

#define T_STEPS 2048
#define N_DIM   512
#define BLOCK   32                     // one warp
#define U       64                     // time-steps per tile
#define NT      (T_STEPS / U)          // 32 tiles
#define STAGES  5
#define TILE_FLOATS (U * BLOCK)        // 2048 floats = 8 KB
#define TILE_BYTES  (TILE_FLOATS * 4)

__device__ __forceinline__ void cp_async16(uint32_t saddr, const void* gaddr) {
    asm volatile("cp.async.cg.shared.global [%0], [%1], 16;\n"
                 :: "r"(saddr), "l"(gaddr));
}
__device__ __forceinline__ void cp_commit() {
    asm volatile("cp.async.commit_group;\n" ::: "memory");
}

__global__ __launch_bounds__(BLOCK)
void exodus_kernel(const float* __restrict__ x,
                   const float* __restrict__ w,
                   float* __restrict__ out) {
    __shared__ float smem[STAGES * TILE_FLOATS];    // 40 KB

    const int tid = threadIdx.x;
    const int b   = blockIdx.x >> 4;            // 32 batches
    const int n0  = (blockIdx.x & 15) * BLOCK;  // 16 n-chunks of 32

    const float weight = w[0];
    const float alpha  = 0.95122942450071400910f;   // exp(-1/20) as f32

    const long gbase = (long)b * (T_STEPS * N_DIM) + n0;
    const float* __restrict__ xblk = x + gbase;
    float* __restrict__ oplane = out + gbase + tid;

    const uint32_t sbase = (uint32_t)__cvta_generic_to_shared(smem);

    // Loader mapping: one row (time-step) = 32 floats = 128 B = 8 x 16 B.
    // chunkCol = tid & 7 spans a row; rowOff = tid >> 3 staggers 4 rows.
    const int chunkCol = tid & 7;
    const int rowOff   = tid >> 3;

    auto issue_tile = [&](int tt) {
        const uint32_t s0 = sbase + (tt % STAGES) * TILE_BYTES
                          + rowOff * 128 + chunkCol * 16;
        const float* g0 = xblk + (long)(tt * U + rowOff) * N_DIM + chunkCol * 4;
        #pragma unroll
        for (int i = 0; i < U / 4; i++)                 // 16 x LDGSTS.128
            cp_async16(s0 + i * 4 * 128, g0 + (long)i * 4 * N_DIM);
        cp_commit();
    };

    // Prologue: 4 tiles in flight
    issue_tile(0);
    issue_tile(1);
    issue_tile(2);
    issue_tile(3);

    float vs = 0.0f, vm = 0.0f;

    for (int tt = 0; tt < NT; tt++) {
        if (tt + 4 < NT) issue_tile(tt + 4);

        // Tile tt ready when at most the newest (groups covering tt+1..) pend.
        const int rem = NT - 1 - tt;                 // tiles after tt
        if      (rem >= 4) asm volatile("cp.async.wait_group 4;\n" ::: "memory");
        else if (rem == 3) asm volatile("cp.async.wait_group 3;\n" ::: "memory");
        else if (rem == 2) asm volatile("cp.async.wait_group 2;\n" ::: "memory");
        else if (rem == 1) asm volatile("cp.async.wait_group 1;\n" ::: "memory");
        else               asm volatile("cp.async.wait_group 0;\n" ::: "memory");
        __syncwarp();    // cross-lane visibility of async-copied data

        const float* __restrict__ srow = smem + (tt % STAGES) * TILE_FLOATS + tid;

        // 4-deep LDS lookahead (48 cyc ahead > 29-cyc LDS latency)
        float xv0 = srow[0 * BLOCK];
        float xv1 = srow[1 * BLOCK];
        float xv2 = srow[2 * BLOCK];
        float xv3 = srow[3 * BLOCK];

        #pragma unroll
        for (int r = 0; r < U; r++) {
            float xn = (r + 4 < U) ? srow[(r + 4) * BLOCK] : 0.0f;
            const float xi  = xv0 * weight;
            vs = fmaf(alpha, vs, xi);               // ExpLeak
            const float vmp = fmaf(alpha, vm, vs);  // LIF integrate
            const bool  spk = (vmp >= 1.0f);
            const float vmr = vmp - 1.0f;           // parallel with compare
            vm = spk ? vmr : vmp;                   // FSEL (pred-as-data)
            __stcs(oplane + (long)(tt * U + r) * N_DIM, spk ? 1.0f : 0.0f);
            xv0 = xv1; xv1 = xv2; xv2 = xv3; xv3 = xn;
        }

        __syncwarp();    // all lanes past tile tt before its stage is reissued
    }
}

extern "C" void kernel_launch(void* const* d_in, const int* in_sizes, int n_in,
                              void* d_out, int out_size) {
    const float* x = (const float*)d_in[0];
    const float* w = (const float*)d_in[1];
    float* out = (float*)d_out;

    exodus_kernel<<<512, BLOCK>>>(x, w, out);   // 512 blocks x 1 warp = 16384 seqs
}

// round 4
// speedup vs baseline: 1.0767x; 1.0767x over previous
#include <cuda_runtime.h>
#include <cstdint>

// ExodusNeuron scan, R4: float2 vectorization (2 sequences per thread) on top
// of the R2 pipeline shape (3-stage cp.async ring, prefetch distance 2,
// static 48 KB smem, 1 warp per block, 256 blocks).
//
// Per-element numerics identical to R1/R2 (rel_err 0.0):
//   xi = x*w ; vs = fma(a,vs,xi) ; vmp = fma(a,vm,vs)
//   spk = vmp >= 1 ; vm = spk ? vmp-1 : vmp

#define T_STEPS 2048
#define N_DIM   512
#define BLOCK   32                     // one warp
#define VEC     2                      // sequences per thread
#define NSEQ    (BLOCK * VEC)          // 64 n per block
#define U       64                     // time-steps per tile
#define NT      (T_STEPS / U)          // 32 tiles
#define STAGES  3
#define TILE_FLOATS (U * NSEQ)         // 4096 floats = 16 KB
#define TILE_BYTES  (TILE_FLOATS * 4)

__device__ __forceinline__ void cp_async16(uint32_t saddr, const void* gaddr) {
    asm volatile("cp.async.cg.shared.global [%0], [%1], 16;\n"
                 :: "r"(saddr), "l"(gaddr));
}
__device__ __forceinline__ void cp_commit() {
    asm volatile("cp.async.commit_group;\n" ::: "memory");
}

__global__ __launch_bounds__(BLOCK)
void exodus_kernel(const float* __restrict__ x,
                   const float* __restrict__ w,
                   float* __restrict__ out) {
    __shared__ float smem[STAGES * TILE_FLOATS];    // 48 KB

    const int tid = threadIdx.x;
    const int b   = blockIdx.x >> 3;           // 32 batches
    const int n0  = (blockIdx.x & 7) * NSEQ;   // 8 n-chunks of 64

    const float weight = w[0];
    const float alpha  = 0.95122942450071400910f;   // exp(-1/20) as f32

    const long gbase = (long)b * (T_STEPS * N_DIM) + n0;
    const float* __restrict__ xblk = x + gbase;
    // lane t owns n0+2t, n0+2t+1 -> float2 at (t_step)*256 + tid (float2 units)
    float2* __restrict__ oplane = (float2*)(out + gbase) + tid;

    const uint32_t sbase = (uint32_t)__cvta_generic_to_shared(smem);

    // Loader: one row (time-step) = 64 floats = 256 B = 16 x 16 B chunks.
    // chunkCol = tid & 15 spans a row; rowOff = tid >> 4 staggers 2 rows.
    const int chunkCol = tid & 15;
    const int rowOff   = tid >> 4;

    auto issue_tile = [&](int tt) {
        const uint32_t s0 = sbase + (tt % STAGES) * TILE_BYTES
                          + rowOff * 256 + chunkCol * 16;
        const float* g0 = xblk + (long)(tt * U + rowOff) * N_DIM + chunkCol * 4;
        #pragma unroll
        for (int i = 0; i < U / 2; i++)                 // 32 x LDGSTS.128
            cp_async16(s0 + i * 2 * 256, g0 + (long)i * 2 * N_DIM);
        cp_commit();
    };

    issue_tile(0);
    issue_tile(1);

    float vs0 = 0.0f, vm0 = 0.0f;
    float vs1 = 0.0f, vm1 = 0.0f;

    for (int tt = 0; tt < NT; tt++) {
        if (tt + 2 < NT) issue_tile(tt + 2);

        const int rem = NT - 1 - tt;
        if      (rem >= 2) asm volatile("cp.async.wait_group 2;\n" ::: "memory");
        else if (rem == 1) asm volatile("cp.async.wait_group 1;\n" ::: "memory");
        else               asm volatile("cp.async.wait_group 0;\n" ::: "memory");
        __syncwarp();

        const float2* __restrict__ srow =
            (const float2*)(smem + (tt % STAGES) * TILE_FLOATS) + tid;

        // 4-deep LDS.64 lookahead
        float2 xv0 = srow[0 * BLOCK];
        float2 xv1 = srow[1 * BLOCK];
        float2 xv2 = srow[2 * BLOCK];
        float2 xv3 = srow[3 * BLOCK];

        #pragma unroll
        for (int r = 0; r < U; r++) {
            float2 xn = (r + 4 < U) ? srow[(r + 4) * BLOCK]
                                    : make_float2(0.0f, 0.0f);
            // two independent scan chains -> ILP hides the 12-cyc vm chain
            const float xiA  = xv0.x * weight;
            const float xiB  = xv0.y * weight;
            vs0 = fmaf(alpha, vs0, xiA);
            vs1 = fmaf(alpha, vs1, xiB);
            const float vmpA = fmaf(alpha, vm0, vs0);
            const float vmpB = fmaf(alpha, vm1, vs1);
            const bool  sA   = (vmpA >= 1.0f);
            const bool  sB   = (vmpB >= 1.0f);
            vm0 = sA ? (vmpA - 1.0f) : vmpA;
            vm1 = sB ? (vmpB - 1.0f) : vmpB;
            float2 sv;
            sv.x = sA ? 1.0f : 0.0f;
            sv.y = sB ? 1.0f : 0.0f;
            __stcs(oplane + (long)(tt * U + r) * (N_DIM / VEC), sv);
            xv0 = xv1; xv1 = xv2; xv2 = xv3; xv3 = xn;
        }

        __syncwarp();   // all lanes done with tile tt before stage reuse
    }
}

extern "C" void kernel_launch(void* const* d_in, const int* in_sizes, int n_in,
                              void* d_out, int out_size) {
    const float* x = (const float*)d_in[0];
    const float* w = (const float*)d_in[1];
    float* out = (float*)d_out;

    exodus_kernel<<<256, BLOCK>>>(x, w, out);  // 256 blocks x 1 warp, 64 seqs each
}